// round 1
// baseline (speedup 1.0000x reference)
#include <cuda_runtime.h>
#include <cstdint>

// TaylorLinearNet2: out[b,o] = d0[o] + sum_k cumprod_k( t[b,o,:] )
//   t[b, o, d] = sum_i x[b,i] * allweight[o,d,i]
// => GEMM  C[M=4096, N=8192] = X[4096,1024] * W^T  where W is row-major [8192,1024]
//    (allweight [O,D,I] flattened over (o,d) is exactly [8192,1024] row-major),
// fused epilogue per 8-consecutive-column group (one o, d = 0..7).

#define KDIM 1024
#define ODIM 1024
#define BM 128
#define BN 128
#define BK 16

__global__ __launch_bounds__(256, 2)
void taylor_fused_gemm(const float* __restrict__ X,    // [4096, 1024]
                       const float* __restrict__ W,    // [8192, 1024]
                       const float* __restrict__ D0,   // [1024]
                       float* __restrict__ OUT)        // [4096, 1024]
{
    __shared__ float As[BM][BK];   // [m][k] : vec4 stores, broadcast scalar reads
    __shared__ float Bs[BK][BN];   // [k][n] : transposed for packed-pair reads

    const int tid = threadIdx.x;
    const int tx  = tid & 15;      // column group (8 cols = one o-group)
    const int ty  = tid >> 4;      // row group (8 rows)
    const int bm  = blockIdx.y * BM;
    const int bn  = blockIdx.x * BN;

    // tile-load mapping: each thread moves 2 float4 from A and 2 from B per tile
    const int r0 = tid >> 2;       // 0..63
    const int c0 = tid & 3;        // float4 column within the 16-wide k-slab
    const int r1 = r0 + 64;

    const float4* Ag  = reinterpret_cast<const float4*>(X + (size_t)bm * KDIM);
    const float4* Bg  = reinterpret_cast<const float4*>(W + (size_t)bn * KDIM);
    const int ldg4 = KDIM / 4;

    // 8 rows x 4 packed f32x2 accumulators (= 8x8 fp32 micro-tile)
    unsigned long long acc[8][4];
    #pragma unroll
    for (int i = 0; i < 8; i++)
        #pragma unroll
        for (int j = 0; j < 4; j++) acc[i][j] = 0ull;

    // prefetch first tile into registers
    float4 pa0 = Ag[r0 * ldg4 + c0];
    float4 pa1 = Ag[r1 * ldg4 + c0];
    float4 pb0 = Bg[r0 * ldg4 + c0];
    float4 pb1 = Bg[r1 * ldg4 + c0];

    for (int k0 = 0; k0 < KDIM; k0 += BK) {
        // commit prefetched tile to shared
        *reinterpret_cast<float4*>(&As[r0][c0 * 4]) = pa0;
        *reinterpret_cast<float4*>(&As[r1][c0 * 4]) = pa1;
        Bs[c0 * 4 + 0][r0] = pb0.x;  Bs[c0 * 4 + 1][r0] = pb0.y;
        Bs[c0 * 4 + 2][r0] = pb0.z;  Bs[c0 * 4 + 3][r0] = pb0.w;
        Bs[c0 * 4 + 0][r1] = pb1.x;  Bs[c0 * 4 + 1][r1] = pb1.y;
        Bs[c0 * 4 + 2][r1] = pb1.z;  Bs[c0 * 4 + 3][r1] = pb1.w;
        __syncthreads();

        // issue next tile's global loads early (register double-buffer)
        if (k0 + BK < KDIM) {
            const int k4 = (k0 + BK) >> 2;
            pa0 = Ag[r0 * ldg4 + k4 + c0];
            pa1 = Ag[r1 * ldg4 + k4 + c0];
            pb0 = Bg[r0 * ldg4 + k4 + c0];
            pb1 = Bg[r1 * ldg4 + k4 + c0];
        }

        #pragma unroll
        for (int kk = 0; kk < BK; kk++) {
            float av[8];
            #pragma unroll
            for (int i = 0; i < 8; i++) av[i] = As[ty * 8 + i][kk];

            const ulonglong2 q0 = *reinterpret_cast<const ulonglong2*>(&Bs[kk][tx * 8]);
            const ulonglong2 q1 = *reinterpret_cast<const ulonglong2*>(&Bs[kk][tx * 8 + 4]);
            const unsigned long long bv0 = q0.x, bv1 = q0.y, bv2 = q1.x, bv3 = q1.y;

            #pragma unroll
            for (int i = 0; i < 8; i++) {
                unsigned long long ap;
                asm("mov.b64 %0, {%1, %1};" : "=l"(ap) : "f"(av[i]));
                asm("fma.rn.f32x2 %0, %1, %2, %0;" : "+l"(acc[i][0]) : "l"(ap), "l"(bv0));
                asm("fma.rn.f32x2 %0, %1, %2, %0;" : "+l"(acc[i][1]) : "l"(ap), "l"(bv1));
                asm("fma.rn.f32x2 %0, %1, %2, %0;" : "+l"(acc[i][2]) : "l"(ap), "l"(bv2));
                asm("fma.rn.f32x2 %0, %1, %2, %0;" : "+l"(acc[i][3]) : "l"(ap), "l"(bv3));
            }
        }
        __syncthreads();
    }

    // Fused Taylor epilogue: this thread's 8 columns are n = bn + tx*8 + (0..7)
    // => exactly d = 0..7 of o = bn/8 + tx.
    const int o = (bn >> 3) + tx;
    const float d0v = D0[o];

    #pragma unroll
    for (int i = 0; i < 8; i++) {
        float t[8];
        #pragma unroll
        for (int j = 0; j < 4; j++) {
            float lo, hi;
            asm("mov.b64 {%0, %1}, %2;" : "=f"(lo), "=f"(hi) : "l"(acc[i][j]));
            t[2 * j]     = lo;
            t[2 * j + 1] = hi;
        }
        float p = t[0];
        float s = p;
        #pragma unroll
        for (int d = 1; d < 8; d++) { p *= t[d]; s += p; }
        OUT[(size_t)(bm + ty * 8 + i) * ODIM + o] = d0v + s;
    }
}

extern "C" void kernel_launch(void* const* d_in, const int* in_sizes, int n_in,
                              void* d_out, int out_size)
{
    const float* x  = (const float*)d_in[0];   // [4096, 1024]
    const float* w  = (const float*)d_in[1];   // [1024, 8, 1024] == [8192, 1024]
    const float* d0 = (const float*)d_in[2];   // [1, 1024]
    float* out = (float*)d_out;                // [4096, 1024]

    dim3 grid(8192 / BN, 4096 / BM);           // (64, 32)
    taylor_fused_gemm<<<grid, 256>>>(x, w, d0, out);
}

// round 4
// speedup vs baseline: 2.0833x; 2.0833x over previous
#include <cuda_runtime.h>
#include <cuda_bf16.h>
#include <cstdint>

// ============================================================================
// TaylorLinearNet2 via HMMA (mma.sync bf16), portable sm_100 target.
//   t = X @ W^T  (M=4096, N=8192, K=1024 fp32), then per-8-col Taylor epilogue.
// fp32 emulated as split-bf16 folded into one K=3072 GEMM:
//   A' = [Xh | Xh | Xl]  (4096 x 3072),  B' = [Wh | Wl | Wh]  (8192 x 3072)
//   x*w ~= xh*wh + xh*wl + xl*wh   (lo*lo ~2^-18, negligible)
// ============================================================================

#define M_TOTAL 4096
#define N_TOTAL 8192
#define K_IN    1024
#define KTOT    3072
#define ODIM    1024

#define BM 128
#define BN 256
#define BK 32
#define STAGES 4
#define NCH (KTOT / BK)        // 96

// padded smem rows: 32 bf16 + 8 pad = 40 elems = 80 B (16B aligned, bank-clean)
#define LDE 40
#define ROWB 80
#define A_BYTES (BM * ROWB)            // 10240
#define B_BYTES (BN * ROWB)            // 20480
#define STAGE_BYTES (A_BYTES + B_BYTES) // 30720
#define SMEM_TOTAL (STAGES * STAGE_BYTES) // 122880

__device__ __align__(128) __nv_bfloat16 g_A[(size_t)M_TOTAL * KTOT]; // 24 MB
__device__ __align__(128) __nv_bfloat16 g_B[(size_t)N_TOTAL * KTOT]; // 48 MB

__device__ __forceinline__ uint32_t smem_u32(const void* p) {
    uint32_t a;
    asm("{ .reg .u64 t; cvta.to.shared.u64 t, %1; cvt.u32.u64 %0, t; }"
        : "=r"(a) : "l"(p));
    return a;
}

#define CP_ASYNC16(dst, src) \
    asm volatile("cp.async.cg.shared.global [%0], [%1], 16;" :: "r"(dst), "l"(src))
#define CP_COMMIT() asm volatile("cp.async.commit_group;" ::: "memory")
#define CP_WAIT(n)  asm volatile("cp.async.wait_group %0;" :: "n"(n) : "memory")

#define LDMATRIX_X4(r0, r1, r2, r3, addr) \
    asm volatile("ldmatrix.sync.aligned.m8n8.x4.shared.b16 {%0,%1,%2,%3}, [%4];" \
                 : "=r"(r0), "=r"(r1), "=r"(r2), "=r"(r3) : "r"(addr))

#define MMA_BF16(acc, a, b0v, b1v) \
    asm volatile("mma.sync.aligned.m16n8k16.row.col.f32.bf16.bf16.f32 " \
                 "{%0,%1,%2,%3}, {%4,%5,%6,%7}, {%8,%9}, {%0,%1,%2,%3};" \
                 : "+f"((acc)[0]), "+f"((acc)[1]), "+f"((acc)[2]), "+f"((acc)[3]) \
                 : "r"((a)[0]), "r"((a)[1]), "r"((a)[2]), "r"((a)[3]), \
                   "r"(b0v), "r"(b1v))

// ============================================================================
// split-bf16 conversion
// ============================================================================
__global__ void convert_x_kernel(const float* __restrict__ X) {
    int idx = blockIdx.x * blockDim.x + threadIdx.x;
    if (idx >= M_TOTAL * K_IN) return;
    int m = idx >> 10, i = idx & 1023;
    float v = X[idx];
    __nv_bfloat16 hi = __float2bfloat16_rn(v);
    __nv_bfloat16 lo = __float2bfloat16_rn(v - __bfloat162float(hi));
    size_t base = (size_t)m * KTOT;
    g_A[base + i]            = hi;  // vs Wh
    g_A[base + K_IN + i]     = hi;  // vs Wl
    g_A[base + 2 * K_IN + i] = lo;  // vs Wh
}

__global__ void convert_w_kernel(const float* __restrict__ W) {
    int idx = blockIdx.x * blockDim.x + threadIdx.x;
    if (idx >= N_TOTAL * K_IN) return;
    int n = idx >> 10, i = idx & 1023;
    float v = W[idx];
    __nv_bfloat16 hi = __float2bfloat16_rn(v);
    __nv_bfloat16 lo = __float2bfloat16_rn(v - __bfloat162float(hi));
    size_t base = (size_t)n * KTOT;
    g_B[base + i]            = hi;
    g_B[base + K_IN + i]     = lo;
    g_B[base + 2 * K_IN + i] = hi;
}

// ============================================================================
// GEMM + fused Taylor epilogue.  grid (N/256, M/128) = (32, 32), 512 threads.
// Warp grid 4(m) x 4(n); warp tile m32 x n64.
// ============================================================================
__global__ __launch_bounds__(512, 1)
void taylor_hmma_kernel(const float* __restrict__ D0, float* __restrict__ OUT)
{
    extern __shared__ __align__(128) char smem[];
    const uint32_t sb = smem_u32(smem);

    const int tid  = threadIdx.x;
    const int lane = tid & 31;
    const int wid  = tid >> 5;
    const int warp_m = wid >> 2;    // 0..3 -> m offset *32
    const int warp_n = wid & 3;     // 0..3 -> n offset *64

    const int bm = blockIdx.y * BM;
    const int bn = blockIdx.x * BN;

    // ---- cp.async source/dest mapping: 3 x 16B per thread per stage ----
    const int grow = tid >> 2;          // 0..127
    const int gc   = tid & 3;           // 16B chunk in 64B k-slab
    const __nv_bfloat16* gA  = g_A + (size_t)(bm + grow) * KTOT + gc * 8;
    const __nv_bfloat16* gB0 = g_B + (size_t)(bn + grow) * KTOT + gc * 8;
    const __nv_bfloat16* gB1 = gB0 + (size_t)128 * KTOT;
    const uint32_t sAd = sb + grow * ROWB + gc * 16;
    const uint32_t sBd0 = sb + A_BYTES + grow * ROWB + gc * 16;
    const uint32_t sBd1 = sBd0 + 128 * ROWB;

    float acc[2][8][4];
    #pragma unroll
    for (int mt = 0; mt < 2; mt++)
        #pragma unroll
        for (int nt = 0; nt < 8; nt++)
            #pragma unroll
            for (int r = 0; r < 4; r++) acc[mt][nt][r] = 0.0f;

    // ---- ldmatrix address precompute (per k16-step add chunk offset) ----
    // A x4: lanes 0-7: m0-7 kLo | 8-15: m8-15 kLo | 16-23: m0-7 kHi | 24-31: m8-15 kHi
    const int a_row  = warp_m * 32 + (lane & 15);
    const int a_chnk = (lane >> 4);            // 0 = kLo(8), 1 = kHi
    // B x4: lanes 0-7: n0-7 kLo | 8-15: n0-7 kHi | 16-23: n8-15 kLo | 24-31: n8-15 kHi
    const int b_row  = warp_n * 64 + (lane & 7) + ((lane >> 4) & 1) * 8;
    const int b_chnk = (lane >> 3) & 1;

    // ---- pipeline prologue ----
    #pragma unroll
    for (int s = 0; s < STAGES - 1; s++) {
        const int k0 = s * BK;
        CP_ASYNC16(sAd  + s * STAGE_BYTES, gA  + k0);
        CP_ASYNC16(sBd0 + s * STAGE_BYTES, gB0 + k0);
        CP_ASYNC16(sBd1 + s * STAGE_BYTES, gB1 + k0);
        CP_COMMIT();
    }

    for (int i = 0; i < NCH; i++) {
        CP_WAIT(STAGES - 2);
        __syncthreads();

        // refill the slot freed at iteration i-1
        if (i + STAGES - 1 < NCH) {
            const int s  = (i + STAGES - 1) & (STAGES - 1);
            const int k0 = (i + STAGES - 1) * BK;
            CP_ASYNC16(sAd  + s * STAGE_BYTES, gA  + k0);
            CP_ASYNC16(sBd0 + s * STAGE_BYTES, gB0 + k0);
            CP_ASYNC16(sBd1 + s * STAGE_BYTES, gB1 + k0);
        }
        CP_COMMIT();   // keep group count in lockstep with iterations

        const uint32_t aBase = sb + (i & (STAGES - 1)) * STAGE_BYTES;
        const uint32_t bBase = aBase + A_BYTES;

        #pragma unroll
        for (int ks = 0; ks < 2; ks++) {            // two k16 steps per BK=32
            uint32_t a[2][4];
            #pragma unroll
            for (int mt = 0; mt < 2; mt++) {
                uint32_t addr = aBase + (a_row + mt * 16) * ROWB
                              + (ks * 2 + a_chnk) * 16;
                LDMATRIX_X4(a[mt][0], a[mt][1], a[mt][2], a[mt][3], addr);
            }
            uint32_t b[4][4];
            #pragma unroll
            for (int np = 0; np < 4; np++) {
                uint32_t addr = bBase + (b_row + np * 16) * ROWB
                              + (ks * 2 + b_chnk) * 16;
                LDMATRIX_X4(b[np][0], b[np][1], b[np][2], b[np][3], addr);
            }
            #pragma unroll
            for (int mt = 0; mt < 2; mt++)
                #pragma unroll
                for (int nt = 0; nt < 8; nt++)
                    MMA_BF16(acc[mt][nt], a[mt],
                             b[nt >> 1][(nt & 1) * 2], b[nt >> 1][(nt & 1) * 2 + 1]);
        }
        __syncthreads();
    }

    // ---- fused Taylor epilogue ----
    // C frag m16n8: c0,c1 -> row = lane>>2, cols 2*(lane&3)+{0,1}; c2,c3 -> row+8.
    // Each n8 tile == one o-group (d = 0..7). Gather the 8 cols across the quad.
    const int q = lane & ~3;
    #pragma unroll
    for (int nt = 0; nt < 8; nt++) {
        const int o = blockIdx.x * 32 + warp_n * 8 + nt;
        const float d0v = D0[o];
        #pragma unroll
        for (int mt = 0; mt < 2; mt++) {
            float c0 = acc[mt][nt][0], c1 = acc[mt][nt][1];
            float c2 = acc[mt][nt][2], c3 = acc[mt][nt][3];
            float t0[8], t1[8];
            #pragma unroll
            for (int d2 = 0; d2 < 4; d2++) {
                t0[2 * d2]     = __shfl_sync(0xffffffffu, c0, q + d2);
                t0[2 * d2 + 1] = __shfl_sync(0xffffffffu, c1, q + d2);
                t1[2 * d2]     = __shfl_sync(0xffffffffu, c2, q + d2);
                t1[2 * d2 + 1] = __shfl_sync(0xffffffffu, c3, q + d2);
            }
            float p0 = t0[0], s0 = t0[0];
            float p1 = t1[0], s1 = t1[0];
            #pragma unroll
            for (int d = 1; d < 8; d++) {
                p0 *= t0[d]; s0 += p0;
                p1 *= t1[d]; s1 += p1;
            }
            if ((lane & 3) == 0) {
                const int m0 = bm + warp_m * 32 + mt * 16 + (lane >> 2);
                OUT[(size_t)m0 * ODIM + o]       = d0v + s0;
                OUT[(size_t)(m0 + 8) * ODIM + o] = d0v + s1;
            }
        }
    }
}

// ============================================================================
// host side
// ============================================================================
extern "C" void kernel_launch(void* const* d_in, const int* in_sizes, int n_in,
                              void* d_out, int out_size)
{
    const float* x  = (const float*)d_in[0];   // [4096, 1024]
    const float* wt = (const float*)d_in[1];   // [1024, 8, 1024] = [8192, 1024]
    const float* d0 = (const float*)d_in[2];   // [1, 1024]
    float* out = (float*)d_out;                // [4096, 1024]

    convert_x_kernel<<<(M_TOTAL * K_IN + 255) / 256, 256>>>(x);
    convert_w_kernel<<<(N_TOTAL * K_IN + 255) / 256, 256>>>(wt);

    cudaFuncSetAttribute(taylor_hmma_kernel,
                         cudaFuncAttributeMaxDynamicSharedMemorySize, SMEM_TOTAL);
    dim3 grid(N_TOTAL / BN, M_TOTAL / BM);     // (32, 32)
    taylor_hmma_kernel<<<grid, 512, SMEM_TOTAL>>>(d0, out);
}